// round 16
// baseline (speedup 1.0000x reference)
#include <cuda_runtime.h>
#include <cuda_bf16.h>
#include <cuda_fp16.h>
#include <cstdint>

// Problem constants
#define BB   4
#define CC   512
#define NN   4096
#define MIDD 64

// ---------------------------------------------------------------------------
// Scratch (__device__ globals; allocation-free rule).
// ---------------------------------------------------------------------------
__device__ __nv_bfloat16 g_xh[(size_t)BB * NN * CC];    // x^T hi  [b][n][c]
__device__ __nv_bfloat16 g_xl[(size_t)BB * NN * CC];    // x^T lo
__device__ __half        g_xf[(size_t)BB * NN * CC];    // x^T fp16
__device__ __nv_bfloat16 g_wqkh[128 * 512];             // [wq;wk] hi
__device__ __nv_bfloat16 g_wqkl[128 * 512];             // [wq;wk] lo
__device__ __half        g_wvf[512 * 512];              // wv fp16
__device__ __nv_bfloat16 g_qh[(size_t)BB * NN * MIDD];
__device__ __nv_bfloat16 g_ql[(size_t)BB * NN * MIDD];
__device__ __nv_bfloat16 g_kh[(size_t)BB * NN * MIDD];
__device__ __nv_bfloat16 g_kl[(size_t)BB * NN * MIDD];
__device__ __half        g_v[(size_t)BB * CC * NN];     // [b][c][n]
__device__ float         g_s[(size_t)BB * NN * NN];     // fp32 logits
__device__ __half        g_p[(size_t)BB * NN * NN];     // fp16 probs (UNNORMALIZED exp)
__device__ unsigned      g_rowmax[(size_t)BB * NN];     // float-ordered keys
__device__ float         g_pinv[(size_t)BB * NN];       // 1/rowsum

static __device__ __forceinline__ unsigned fkey(float f) {
    unsigned b = __float_as_uint(f);
    return (b & 0x80000000u) ? ~b : (b | 0x80000000u);
}
static __device__ __forceinline__ float funkey(unsigned k) {
    unsigned b = (k & 0x80000000u) ? (k & 0x7fffffffu) : ~k;
    return __uint_as_float(b);
}

static __device__ __forceinline__ void split2(float a, float b, uint32_t& h, uint32_t& l) {
    __nv_bfloat16 ha = __float2bfloat16_rn(a);
    __nv_bfloat16 hb = __float2bfloat16_rn(b);
    __nv_bfloat16 la = __float2bfloat16_rn(a - __bfloat162float(ha));
    __nv_bfloat16 lb = __float2bfloat16_rn(b - __bfloat162float(hb));
    __nv_bfloat162 th; th.x = ha; th.y = hb;
    __nv_bfloat162 tl; tl.x = la; tl.y = lb;
    h = *(uint32_t*)&th;  l = *(uint32_t*)&tl;
}
static __device__ __forceinline__ uint32_t packh2(float a, float b) {
    __half2 t = __floats2half2_rn(a, b);
    return *(uint32_t*)&t;
}

#define MMA_BF16(d, a, b)                                                     \
    asm volatile(                                                             \
        "mma.sync.aligned.m16n8k16.row.col.f32.bf16.bf16.f32 "                \
        "{%0,%1,%2,%3}, {%4,%5,%6,%7}, {%8,%9}, {%0,%1,%2,%3};"               \
        : "+f"(d[0]), "+f"(d[1]), "+f"(d[2]), "+f"(d[3])                      \
        : "r"(a[0]), "r"(a[1]), "r"(a[2]), "r"(a[3]), "r"(b[0]), "r"(b[1]))

#define MMA_F16(d, a, b)                                                      \
    asm volatile(                                                             \
        "mma.sync.aligned.m16n8k16.row.col.f32.f16.f16.f32 "                  \
        "{%0,%1,%2,%3}, {%4,%5,%6,%7}, {%8,%9}, {%0,%1,%2,%3};"               \
        : "+f"(d[0]), "+f"(d[1]), "+f"(d[2]), "+f"(d[3])                      \
        : "r"(a[0]), "r"(a[1]), "r"(a[2]), "r"(a[3]), "r"(b[0]), "r"(b[1]))

static __device__ __forceinline__ void cp16(uint32_t s, const void* g) {
    asm volatile("cp.async.cg.shared.global [%0], [%1], 16;\n" :: "r"(s), "l"(g) : "memory");
}
#define CP_COMMIT() asm volatile("cp.async.commit_group;\n" ::: "memory")

static __device__ __forceinline__ void ldsm4(uint32_t* r, uint32_t addr) {
    asm volatile("ldmatrix.sync.aligned.m8n8.x4.shared.b16 {%0,%1,%2,%3}, [%4];"
                 : "=r"(r[0]), "=r"(r[1]), "=r"(r[2]), "=r"(r[3]) : "r"(addr));
}

// Fragment loaders for k-major tiles with runtime row stride (in halves).
#define PSTR 40
static __device__ __forceinline__ void lda4(uint32_t a[4][4], uint32_t sb,
                                            int wm, int lane, int kc, int str) {
    int rbase = wm * 64 + (lane & 7) + ((lane & 8) ? 8 : 0);
    int kcol = kc * 16 + ((lane & 16) ? 8 : 0);
    #pragma unroll
    for (int mi = 0; mi < 4; mi++)
        ldsm4(a[mi], sb + (uint32_t)(((rbase + mi * 16) * str + kcol) * 2));
}
static __device__ __forceinline__ void ldb4(uint32_t bf[][2], uint32_t sb,
                                            int wn, int lane, int kc, int str) {
    int rb = wn * 32 + (lane & 7) + ((lane & 16) ? 8 : 0);
    int kcol = kc * 16 + ((lane & 8) ? 8 : 0);
    #pragma unroll
    for (int nip = 0; nip < 4; nip += 2) {
        uint32_t r[4];
        ldsm4(r, sb + (uint32_t)(((rb + nip * 8) * str + kcol) * 2));
        bf[nip][0] = r[0]; bf[nip][1] = r[1];
        bf[nip + 1][0] = r[2]; bf[nip + 1][1] = r[3];
    }
}

// ---------------------------------------------------------------------------
// Kernel A: transpose+convert x[b][c][n] -> xh/xl (bf16 split), xf (fp16), [b][n][c]
// ---------------------------------------------------------------------------
__global__ __launch_bounds__(256)
void xconv_kernel(const float* __restrict__ x) {
    __shared__ float t[64][65];
    const int n0 = blockIdx.x * 64, c0 = blockIdx.y * 64, b = blockIdx.z;
    const int tid = threadIdx.x;
    const float* xb = x + ((size_t)b * CC + c0) * NN + n0;
    #pragma unroll
    for (int i = tid; i < 1024; i += 256) {
        int r = i >> 4, q = i & 15;
        float4 v = *(const float4*)&xb[(size_t)r * NN + q * 4];
        t[r][q * 4 + 0] = v.x; t[r][q * 4 + 1] = v.y;
        t[r][q * 4 + 2] = v.z; t[r][q * 4 + 3] = v.w;
    }
    __syncthreads();
    #pragma unroll
    for (int i = tid; i < 1024; i += 256) {
        int n = i >> 4, qd = i & 15;
        float v0 = t[qd * 4 + 0][n], v1 = t[qd * 4 + 1][n];
        float v2 = t[qd * 4 + 2][n], v3 = t[qd * 4 + 3][n];
        uint2 uh, ul, uf;
        split2(v0, v1, uh.x, ul.x);
        split2(v2, v3, uh.y, ul.y);
        uf.x = packh2(v0, v1); uf.y = packh2(v2, v3);
        size_t off = ((size_t)b * NN + n0 + n) * CC + c0 + qd * 4;
        *(uint2*)&g_xh[off] = uh;
        *(uint2*)&g_xl[off] = ul;
        *(uint2*)&g_xf[off] = uf;
    }
}

// ---------------------------------------------------------------------------
// Kernel B: weight conversion + rowmax init.
// ---------------------------------------------------------------------------
__global__ __launch_bounds__(256)
void wconv_kernel(const float* __restrict__ wq, const float* __restrict__ wk,
                  const float* __restrict__ wv) {
    int idx = blockIdx.x * 256 + threadIdx.x;
    if (idx < 128 * 512) {
        int m = idx >> 9, k = idx & 511;
        float v = (m < 64) ? wq[m * 512 + k] : wk[(m - 64) * 512 + k];
        __nv_bfloat16 h = __float2bfloat16_rn(v);
        g_wqkh[idx] = h;
        g_wqkl[idx] = __float2bfloat16_rn(v - __bfloat162float(h));
    } else {
        int j = idx - 65536;
        if (j < 262144) g_wvf[j] = __float2half_rn(wv[j]);
    }
    if (idx < BB * NN) g_rowmax[idx] = 0u;   // smallest key
}

// ---------------------------------------------------------------------------
// Kernel C: q/k projection via 3-pass split-bf16 HMMA.
// ---------------------------------------------------------------------------
#define TSTR_H (128 * PSTR)               // 5120 halves per 128x32 stream
#define QK_STG_H (4 * TSTR_H)             // xh | xl | wh | wl
#define QK_SMEM (3 * QK_STG_H * 2)

__global__ __launch_bounds__(256)
void proj_qk_kernel(const float* __restrict__ bq, const float* __restrict__ bk) {
    const int n0 = blockIdx.x * 128, b = blockIdx.z;
    extern __shared__ __align__(16) __nv_bfloat16 qsm[];
    const uint32_t sbase = (uint32_t)__cvta_generic_to_shared(qsm);

    const int tid = threadIdx.x;
    const int wid = tid >> 5, lane = tid & 31;
    const int wm = wid >> 2, wn = wid & 3;
    const int g = lane >> 2, c = lane & 3;

    const __nv_bfloat16* xh = g_xh + ((size_t)b * NN + n0) * CC;
    const __nv_bfloat16* xl = g_xl + ((size_t)b * NN + n0) * CC;

    const int lr = tid >> 1, lc0 = (tid & 1) * 2;

    auto load_tile = [&](int stage, int k0) {
        uint32_t st = sbase + (uint32_t)(stage * QK_STG_H * 2);
        #pragma unroll
        for (int q = 0; q < 2; q++) {
            int c8 = lc0 + q;
            uint32_t so = lr * (PSTR * 2) + c8 * 16;
            cp16(st + so,                 &xh[(size_t)lr * CC + k0 + c8 * 8]);
            cp16(st + TSTR_H * 2 + so,    &xl[(size_t)lr * CC + k0 + c8 * 8]);
            cp16(st + TSTR_H * 4 + so,    &g_wqkh[lr * 512 + k0 + c8 * 8]);
            cp16(st + TSTR_H * 6 + so,    &g_wqkl[lr * 512 + k0 + c8 * 8]);
        }
        CP_COMMIT();
    };

    load_tile(0, 0);
    load_tile(1, 32);

    float acc[4][4][4] = {};
    const int NT = 512 / 32;   // 16

    for (int jt = 0; jt < NT; jt++) {
        if (jt == NT - 1) asm volatile("cp.async.wait_group 0;\n" ::: "memory");
        else              asm volatile("cp.async.wait_group 1;\n" ::: "memory");
        __syncthreads();
        if (jt + 2 < NT) load_tile((jt + 2) % 3, (jt + 2) * 32);

        uint32_t st = sbase + (uint32_t)((jt % 3) * QK_STG_H * 2);
        #pragma unroll
        for (int kc = 0; kc < 2; kc++) {
            uint32_t afh[4][4], afl[4][4], bfh[4][2], bfl[4][2];
            lda4(afh, st,               wm, lane, kc, PSTR);
            lda4(afl, st + TSTR_H * 2,  wm, lane, kc, PSTR);
            ldb4(bfh, st + TSTR_H * 4,  wn, lane, kc, PSTR);
            ldb4(bfl, st + TSTR_H * 6,  wn, lane, kc, PSTR);
            #pragma unroll
            for (int mi = 0; mi < 4; mi++)
                #pragma unroll
                for (int ni = 0; ni < 4; ni++) {
                    MMA_BF16(acc[mi][ni], afh[mi], bfh[ni]);
                    MMA_BF16(acc[mi][ni], afh[mi], bfl[ni]);
                    MMA_BF16(acc[mi][ni], afl[mi], bfh[ni]);
                }
        }
    }

    #pragma unroll
    for (int ni = 0; ni < 4; ni++) {
        int col = wn * 32 + ni * 8 + 2 * c;
        bool isq = (col < 64);
        const float* bb = isq ? bq : bk;
        int cm = col & 63;
        float b0 = bb[cm], b1 = bb[cm + 1];
        __nv_bfloat16* dh = isq ? g_qh : g_kh;
        __nv_bfloat16* dl = isq ? g_ql : g_kl;
        #pragma unroll
        for (int mi = 0; mi < 4; mi++) {
            int r = n0 + wm * 64 + mi * 16 + g;
            uint32_t uh, ul;
            split2(acc[mi][ni][0] + b0, acc[mi][ni][1] + b1, uh, ul);
            size_t o0 = ((size_t)b * NN + r) * MIDD + cm;
            *(uint32_t*)&dh[o0] = uh;
            *(uint32_t*)&dl[o0] = ul;
            split2(acc[mi][ni][2] + b0, acc[mi][ni][3] + b1, uh, ul);
            size_t o1 = ((size_t)b * NN + r + 8) * MIDD + cm;
            *(uint32_t*)&dh[o1] = uh;
            *(uint32_t*)&dl[o1] = ul;
        }
    }
}

// ---------------------------------------------------------------------------
// Kernel D: V projection via single-pass fp16 HMMA.
// ---------------------------------------------------------------------------
#define V_STG_H (2 * TSTR_H)
#define V_SMEM (3 * V_STG_H * 2)

__global__ __launch_bounds__(256)
void proj_v_kernel(const float* __restrict__ bv) {
    const int n0 = blockIdx.x * 128, c0 = blockIdx.y * 128, b = blockIdx.z;
    extern __shared__ __align__(16) __half vsm[];
    const uint32_t sbase = (uint32_t)__cvta_generic_to_shared(vsm);

    const int tid = threadIdx.x;
    const int wid = tid >> 5, lane = tid & 31;
    const int wm = wid >> 2, wn = wid & 3;
    const int g = lane >> 2, c = lane & 3;

    const __half* wv = g_wvf + (size_t)c0 * 512;
    const __half* xf = g_xf + ((size_t)b * NN + n0) * CC;

    const int lr = tid >> 1, lc0 = (tid & 1) * 2;

    auto load_tile = [&](int stage, int k0) {
        uint32_t st = sbase + (uint32_t)(stage * V_STG_H * 2);
        #pragma unroll
        for (int q = 0; q < 2; q++) {
            int c8 = lc0 + q;
            uint32_t so = lr * (PSTR * 2) + c8 * 16;
            cp16(st + so,              &wv[(size_t)lr * 512 + k0 + c8 * 8]);
            cp16(st + TSTR_H * 2 + so, &xf[(size_t)lr * CC + k0 + c8 * 8]);
        }
        CP_COMMIT();
    };

    load_tile(0, 0);
    load_tile(1, 32);

    float acc[4][4][4] = {};
    const int NT = 512 / 32;

    for (int jt = 0; jt < NT; jt++) {
        if (jt == NT - 1) asm volatile("cp.async.wait_group 0;\n" ::: "memory");
        else              asm volatile("cp.async.wait_group 1;\n" ::: "memory");
        __syncthreads();
        if (jt + 2 < NT) load_tile((jt + 2) % 3, (jt + 2) * 32);

        uint32_t st = sbase + (uint32_t)((jt % 3) * V_STG_H * 2);
        #pragma unroll
        for (int kc = 0; kc < 2; kc++) {
            uint32_t af[4][4], bf[4][2];
            lda4(af, st,              wm, lane, kc, PSTR);
            ldb4(bf, st + TSTR_H * 2, wn, lane, kc, PSTR);
            #pragma unroll
            for (int mi = 0; mi < 4; mi++)
                #pragma unroll
                for (int ni = 0; ni < 4; ni++)
                    MMA_F16(acc[mi][ni], af[mi], bf[ni]);
        }
    }

    #pragma unroll
    for (int mi = 0; mi < 4; mi++) {
        int cc = c0 + wm * 64 + mi * 16 + g;
        float b0 = bv[cc], b2 = bv[cc + 8];
        #pragma unroll
        for (int ni = 0; ni < 4; ni++) {
            int nn = n0 + wn * 32 + ni * 8 + 2 * c;
            size_t o0 = ((size_t)b * CC + cc) * NN + nn;
            *(uint32_t*)&g_v[o0] = packh2(acc[mi][ni][0] + b0, acc[mi][ni][1] + b0);
            size_t o1 = o0 + (size_t)8 * NN;
            *(uint32_t*)&g_v[o1] = packh2(acc[mi][ni][2] + b2, acc[mi][ni][3] + b2);
        }
    }
}

// ---------------------------------------------------------------------------
// Kernel 2: logits via split-bf16 HMMA (3 passes), 128x128 CTA tile (proven
// R12 shape, 2 CTAs/SM). Epilogue additionally computes per-row max -> g_rowmax.
// ---------------------------------------------------------------------------
#define LSTR 72
#define LOGITS_SMEM (4 * 128 * LSTR * 2)

__global__ __launch_bounds__(256)
void logits_kernel() {
    const int j0 = blockIdx.x * 128;
    const int i0 = blockIdx.y * 128;
    const int b  = blockIdx.z;

    extern __shared__ __align__(16) __nv_bfloat16 lsm[];
    __nv_bfloat16* sQh = lsm;
    __nv_bfloat16* sQl = lsm + 128 * LSTR;
    __nv_bfloat16* sKh = lsm + 2 * 128 * LSTR;
    __nv_bfloat16* sKl = lsm + 3 * 128 * LSTR;

    const int tid = threadIdx.x;
    const int wid = tid >> 5, lane = tid & 31;
    const int wm = wid >> 2, wn = wid & 3;
    const int g = lane >> 2, c = lane & 3;

    const size_t qoff = (size_t)b * NN * MIDD;

    #pragma unroll
    for (int i = tid; i < 1024; i += 256) {
        int r = i >> 3, c8 = i & 7;
        size_t go = qoff + (size_t)(i0 + r) * MIDD + c8 * 8;
        size_t ko = qoff + (size_t)(j0 + r) * MIDD + c8 * 8;
        int so = r * LSTR + c8 * 8;
        *(uint4*)&sQh[so] = *(const uint4*)&g_qh[go];
        *(uint4*)&sQl[so] = *(const uint4*)&g_ql[go];
        *(uint4*)&sKh[so] = *(const uint4*)&g_kh[ko];
        *(uint4*)&sKl[so] = *(const uint4*)&g_kl[ko];
    }
    __syncthreads();

    float acc[4][4][4] = {};

    #pragma unroll
    for (int kc = 0; kc < 4; kc++) {
        uint32_t afh[4][4], afl[4][4], bfh[4][2], bfl[4][2];
        #pragma unroll
        for (int mi = 0; mi < 4; mi++) {
            int o = (wm * 64 + mi * 16 + g) * LSTR + kc * 16 + 2 * c;
            afh[mi][0] = *(const uint32_t*)&sQh[o];
            afh[mi][1] = *(const uint32_t*)&sQh[o + 8 * LSTR];
            afh[mi][2] = *(const uint32_t*)&sQh[o + 8];
            afh[mi][3] = *(const uint32_t*)&sQh[o + 8 * LSTR + 8];
            afl[mi][0] = *(const uint32_t*)&sQl[o];
            afl[mi][1] = *(const uint32_t*)&sQl[o + 8 * LSTR];
            afl[mi][2] = *(const uint32_t*)&sQl[o + 8];
            afl[mi][3] = *(const uint32_t*)&sQl[o + 8 * LSTR + 8];
        }
        #pragma unroll
        for (int ni = 0; ni < 4; ni++) {
            int o = (wn * 32 + ni * 8 + g) * LSTR + kc * 16 + 2 * c;
            bfh[ni][0] = *(const uint32_t*)&sKh[o];
            bfh[ni][1] = *(const uint32_t*)&sKh[o + 8];
            bfl[ni][0] = *(const uint32_t*)&sKl[o];
            bfl[ni][1] = *(const uint32_t*)&sKl[o + 8];
        }
        #pragma unroll
        for (int mi = 0; mi < 4; mi++)
            #pragma unroll
            for (int ni = 0; ni < 4; ni++) {
                MMA_BF16(acc[mi][ni], afh[mi], bfh[ni]);
                MMA_BF16(acc[mi][ni], afh[mi], bfl[ni]);
                MMA_BF16(acc[mi][ni], afl[mi], bfh[ni]);
            }
    }

    // store S + per-row max (rows wm*64+mi*16+g and +8)
    float* sbp = g_s + ((size_t)b * NN + i0) * NN + j0;
    #pragma unroll
    for (int mi = 0; mi < 4; mi++) {
        float m0 = -3.4e38f, m1 = -3.4e38f;
        #pragma unroll
        for (int ni = 0; ni < 4; ni++) {
            int r = wm * 64 + mi * 16 + g;
            int cn = wn * 32 + ni * 8 + 2 * c;
            float2 v0 = {acc[mi][ni][0], acc[mi][ni][1]};
            float2 v1 = {acc[mi][ni][2], acc[mi][ni][3]};
            *(float2*)&sbp[(size_t)r * NN + cn] = v0;
            *(float2*)&sbp[(size_t)(r + 8) * NN + cn] = v1;
            m0 = fmaxf(m0, fmaxf(v0.x, v0.y));
            m1 = fmaxf(m1, fmaxf(v1.x, v1.y));
        }
        // reduce over the 4 lanes sharing row r (c = 0..3)
        m0 = fmaxf(m0, __shfl_xor_sync(0xffffffffu, m0, 1));
        m0 = fmaxf(m0, __shfl_xor_sync(0xffffffffu, m0, 2));
        m1 = fmaxf(m1, __shfl_xor_sync(0xffffffffu, m1, 1));
        m1 = fmaxf(m1, __shfl_xor_sync(0xffffffffu, m1, 2));
        if (c == 0) {
            int r = i0 + wm * 64 + mi * 16 + g;
            atomicMax(&g_rowmax[(size_t)b * NN + r], fkey(m0));
            atomicMax(&g_rowmax[(size_t)b * NN + r + 8], fkey(m1));
        }
    }
}

// ---------------------------------------------------------------------------
// Kernel 3: one-pass softmax. Reads fp32 logits + precomputed row max, writes
// UNNORMALIZED fp16 exp(s - m) and 1/rowsum.
// ---------------------------------------------------------------------------
__global__ __launch_bounds__(256, 8)
void softmax_kernel() {
    const int row = blockIdx.x;
    const int b   = blockIdx.y;
    const float* s = g_s + ((size_t)b * NN + row) * NN;
    __half* p = g_p + ((size_t)b * NN + row) * NN;

    const int tid = threadIdx.x;
    const float m = funkey(g_rowmax[(size_t)b * NN + row]);

    float4 v[4];
    #pragma unroll
    for (int i = 0; i < 4; i++)
        v[i] = *(const float4*)&s[tid * 16 + i * 4];

    float sum = 0.f;
    uint32_t hh[8];
    #pragma unroll
    for (int i = 0; i < 4; i++) {
        v[i].x = __expf(v[i].x - m); sum += v[i].x;
        v[i].y = __expf(v[i].y - m); sum += v[i].y;
        v[i].z = __expf(v[i].z - m); sum += v[i].z;
        v[i].w = __expf(v[i].w - m); sum += v[i].w;
        hh[2 * i]     = packh2(v[i].x, v[i].y);
        hh[2 * i + 1] = packh2(v[i].z, v[i].w);
    }
    uint4 u;
    u = make_uint4(hh[0], hh[1], hh[2], hh[3]); *(uint4*)&p[tid * 16] = u;
    u = make_uint4(hh[4], hh[5], hh[6], hh[7]); *(uint4*)&p[tid * 16 + 8] = u;

    __shared__ float red[8];
    #pragma unroll
    for (int off = 16; off > 0; off >>= 1)
        sum += __shfl_xor_sync(0xffffffffu, sum, off);
    if ((tid & 31) == 0) red[tid >> 5] = sum;
    __syncthreads();
    if (tid == 0) {
        float t = 0.f;
        #pragma unroll
        for (int w = 0; w < 8; w++) t += red[w];
        g_pinv[(size_t)b * NN + row] = 1.0f / t;
    }
}

// ---------------------------------------------------------------------------
// Kernel 4: PV via fp16 HMMA, 64x64 warp tiles (CTA 128c x 256n), ldmatrix,
// 3-stage cp.async pipeline. Normalization (1/rowsum) folded into epilogue.
// ---------------------------------------------------------------------------
#define PV_V_H   (128 * PSTR)
#define PV_P_H   (256 * PSTR)
#define PV_STG_H (PV_V_H + PV_P_H)
#define PV_SMEM  (3 * PV_STG_H * 2)

__global__ __launch_bounds__(256, 1)
void pv_kernel(const float* __restrict__ x,
               const float* __restrict__ alpha,
               float* __restrict__ y) {
    const int n0 = blockIdx.x * 256;
    const int c0 = blockIdx.y * 128;
    const int b  = blockIdx.z;

    extern __shared__ __align__(16) __half psm[];
    const uint32_t sbase = (uint32_t)__cvta_generic_to_shared(psm);

    const int tid = threadIdx.x;
    const int wid = tid >> 5, lane = tid & 31;
    const int wm = wid >> 2, wn = wid & 3;
    const int g = lane >> 2, c = lane & 3;

    const __half* vv = g_v + (size_t)(b * CC + c0) * NN;
    const __half* pp = g_p + ((size_t)b * NN + n0) * NN;

    auto load_tile = [&](int stage, int j0) {
        uint32_t st = sbase + (uint32_t)(stage * PV_STG_H * 2);
        #pragma unroll
        for (int i = tid; i < 512; i += 256) {
            int r = i >> 2, ch = i & 3;
            cp16(st + r * (PSTR * 2) + ch * 16, &vv[(size_t)r * NN + j0 + ch * 8]);
        }
        #pragma unroll
        for (int i = tid; i < 1024; i += 256) {
            int r = i >> 2, ch = i & 3;
            cp16(st + PV_V_H * 2 + r * (PSTR * 2) + ch * 16,
                 &pp[(size_t)r * NN + j0 + ch * 8]);
        }
        CP_COMMIT();
    };

    load_tile(0, 0);
    load_tile(1, 32);

    float acc[4][8][4] = {};
    const int NT = NN / 32;   // 128

    for (int jt = 0; jt < NT; jt++) {
        if (jt == NT - 1) asm volatile("cp.async.wait_group 0;\n" ::: "memory");
        else              asm volatile("cp.async.wait_group 1;\n" ::: "memory");
        __syncthreads();
        if (jt + 2 < NT) load_tile((jt + 2) % 3, (jt + 2) * 32);

        uint32_t st = sbase + (uint32_t)((jt % 3) * PV_STG_H * 2);
        #pragma unroll
        for (int kc = 0; kc < 2; kc++) {
            uint32_t af[4][4], bf[8][2];
            lda4(af, st, wm, lane, kc, PSTR);
            ldb4(bf,     st + PV_V_H * 2, wn * 2,     lane, kc, PSTR);
            ldb4(bf + 4, st + PV_V_H * 2, wn * 2 + 1, lane, kc, PSTR);
            #pragma unroll
            for (int mi = 0; mi < 4; mi++)
                #pragma unroll
                for (int ni = 0; ni < 8; ni++)
                    MMA_F16(acc[mi][ni], af[mi], bf[ni]);
        }
    }

    const float al = __ldg(alpha);
    const float* pinv = g_pinv + (size_t)b * NN;
    #pragma unroll
    for (int ni = 0; ni < 8; ni++) {
        int nn = n0 + wn * 64 + ni * 8 + 2 * c;
        float2 iv = *(const float2*)&pinv[nn];
        float s0 = al * iv.x, s1 = al * iv.y;
        #pragma unroll
        for (int mi = 0; mi < 4; mi++) {
            int cc = c0 + wm * 64 + mi * 16 + g;
            size_t o0 = ((size_t)b * CC + cc) * NN + nn;
            float2 xv = *(const float2*)&x[o0];
            float2 o;
            o.x = s0 * acc[mi][ni][0] + xv.x;
            o.y = s1 * acc[mi][ni][1] + xv.y;
            *(float2*)&y[o0] = o;
            size_t o1 = o0 + (size_t)8 * NN;
            xv = *(const float2*)&x[o1];
            o.x = s0 * acc[mi][ni][2] + xv.x;
            o.y = s1 * acc[mi][ni][3] + xv.y;
            *(float2*)&y[o1] = o;
        }
    }
}

// ---------------------------------------------------------------------------
extern "C" void kernel_launch(void* const* d_in, const int* in_sizes, int n_in,
                              void* d_out, int out_size) {
    const float* x     = (const float*)d_in[0];
    const float* wq    = (const float*)d_in[1];
    const float* bq    = (const float*)d_in[2];
    const float* wk    = (const float*)d_in[3];
    const float* bk    = (const float*)d_in[4];
    const float* wv    = (const float*)d_in[5];
    const float* bv    = (const float*)d_in[6];
    const float* alpha = (const float*)d_in[7];
    float* y = (float*)d_out;

    cudaFuncSetAttribute(proj_qk_kernel,
                         cudaFuncAttributeMaxDynamicSharedMemorySize, QK_SMEM);
    cudaFuncSetAttribute(proj_v_kernel,
                         cudaFuncAttributeMaxDynamicSharedMemorySize, V_SMEM);
    cudaFuncSetAttribute(logits_kernel,
                         cudaFuncAttributeMaxDynamicSharedMemorySize, LOGITS_SMEM);
    cudaFuncSetAttribute(pv_kernel,
                         cudaFuncAttributeMaxDynamicSharedMemorySize, PV_SMEM);

    dim3 blk(256);

    xconv_kernel<<<dim3(NN / 64, CC / 64, BB), blk>>>(x);
    wconv_kernel<<<1280, blk>>>(wq, wk, wv);
    proj_qk_kernel<<<dim3(NN / 128, 1, BB), blk, QK_SMEM>>>(bq, bk);
    proj_v_kernel<<<dim3(NN / 128, CC / 128, BB), blk, V_SMEM>>>(bv);
    logits_kernel<<<dim3(NN / 128, NN / 128, BB), blk, LOGITS_SMEM>>>();
    softmax_kernel<<<dim3(NN, BB), blk>>>();
    pv_kernel<<<dim3(NN / 256, CC / 128, BB), blk, PV_SMEM>>>(x, alpha, y);
}

// round 17
// speedup vs baseline: 1.0607x; 1.0607x over previous
#include <cuda_runtime.h>
#include <cuda_bf16.h>
#include <cuda_fp16.h>
#include <cstdint>

// Problem constants
#define BB   4
#define CC   512
#define NN   4096
#define MIDD 64

// ---------------------------------------------------------------------------
// Scratch (__device__ globals; allocation-free rule).
// ---------------------------------------------------------------------------
__device__ __nv_bfloat16 g_xh[(size_t)BB * NN * CC];    // x^T hi  [b][n][c]
__device__ __nv_bfloat16 g_xl[(size_t)BB * NN * CC];    // x^T lo
__device__ __half        g_xf[(size_t)BB * NN * CC];    // x^T fp16
__device__ __nv_bfloat16 g_wqkh[128 * 512];             // [wq;wk] hi
__device__ __nv_bfloat16 g_wqkl[128 * 512];             // [wq;wk] lo
__device__ __half        g_wvf[512 * 512];              // wv fp16
__device__ __nv_bfloat16 g_qh[(size_t)BB * NN * MIDD];
__device__ __nv_bfloat16 g_ql[(size_t)BB * NN * MIDD];
__device__ __nv_bfloat16 g_kh[(size_t)BB * NN * MIDD];
__device__ __nv_bfloat16 g_kl[(size_t)BB * NN * MIDD];
__device__ __half        g_v[(size_t)BB * CC * NN];     // [b][c][n]
__device__ float         g_s[(size_t)BB * NN * NN];     // fp32 logits
__device__ __half        g_p[(size_t)BB * NN * NN];     // fp16 probs

static __device__ __forceinline__ void split2(float a, float b, uint32_t& h, uint32_t& l) {
    __nv_bfloat16 ha = __float2bfloat16_rn(a);
    __nv_bfloat16 hb = __float2bfloat16_rn(b);
    __nv_bfloat16 la = __float2bfloat16_rn(a - __bfloat162float(ha));
    __nv_bfloat16 lb = __float2bfloat16_rn(b - __bfloat162float(hb));
    __nv_bfloat162 th; th.x = ha; th.y = hb;
    __nv_bfloat162 tl; tl.x = la; tl.y = lb;
    h = *(uint32_t*)&th;  l = *(uint32_t*)&tl;
}
static __device__ __forceinline__ uint32_t packh2(float a, float b) {
    __half2 t = __floats2half2_rn(a, b);
    return *(uint32_t*)&t;
}

#define MMA_BF16(d, a, b)                                                     \
    asm volatile(                                                             \
        "mma.sync.aligned.m16n8k16.row.col.f32.bf16.bf16.f32 "                \
        "{%0,%1,%2,%3}, {%4,%5,%6,%7}, {%8,%9}, {%0,%1,%2,%3};"               \
        : "+f"(d[0]), "+f"(d[1]), "+f"(d[2]), "+f"(d[3])                      \
        : "r"(a[0]), "r"(a[1]), "r"(a[2]), "r"(a[3]), "r"(b[0]), "r"(b[1]))

#define MMA_F16(d, a, b)                                                      \
    asm volatile(                                                             \
        "mma.sync.aligned.m16n8k16.row.col.f32.f16.f16.f32 "                  \
        "{%0,%1,%2,%3}, {%4,%5,%6,%7}, {%8,%9}, {%0,%1,%2,%3};"               \
        : "+f"(d[0]), "+f"(d[1]), "+f"(d[2]), "+f"(d[3])                      \
        : "r"(a[0]), "r"(a[1]), "r"(a[2]), "r"(a[3]), "r"(b[0]), "r"(b[1]))

static __device__ __forceinline__ void cp16(uint32_t s, const void* g) {
    asm volatile("cp.async.cg.shared.global [%0], [%1], 16;\n" :: "r"(s), "l"(g) : "memory");
}
#define CP_COMMIT() asm volatile("cp.async.commit_group;\n" ::: "memory")

static __device__ __forceinline__ void ldsm4(uint32_t* r, uint32_t addr) {
    asm volatile("ldmatrix.sync.aligned.m8n8.x4.shared.b16 {%0,%1,%2,%3}, [%4];"
                 : "=r"(r[0]), "=r"(r[1]), "=r"(r[2]), "=r"(r[3]) : "r"(addr));
}

// Fragment loaders for k-major tiles with runtime row stride (in halves).
#define PSTR 40
static __device__ __forceinline__ void lda4(uint32_t a[4][4], uint32_t sb,
                                            int wm, int lane, int kc, int str) {
    int rbase = wm * 64 + (lane & 7) + ((lane & 8) ? 8 : 0);
    int kcol = kc * 16 + ((lane & 16) ? 8 : 0);
    #pragma unroll
    for (int mi = 0; mi < 4; mi++)
        ldsm4(a[mi], sb + (uint32_t)(((rbase + mi * 16) * str + kcol) * 2));
}
static __device__ __forceinline__ void ldb4(uint32_t bf[][2], uint32_t sb,
                                            int wn, int lane, int kc, int str) {
    int rb = wn * 32 + (lane & 7) + ((lane & 16) ? 8 : 0);
    int kcol = kc * 16 + ((lane & 8) ? 8 : 0);
    #pragma unroll
    for (int nip = 0; nip < 4; nip += 2) {
        uint32_t r[4];
        ldsm4(r, sb + (uint32_t)(((rb + nip * 8) * str + kcol) * 2));
        bf[nip][0] = r[0]; bf[nip][1] = r[1];
        bf[nip + 1][0] = r[2]; bf[nip + 1][1] = r[3];
    }
}

// ---------------------------------------------------------------------------
// Kernel A: transpose+convert x[b][c][n] -> xh/xl (bf16 split), xf (fp16), [b][n][c]
// ---------------------------------------------------------------------------
__global__ __launch_bounds__(256)
void xconv_kernel(const float* __restrict__ x) {
    __shared__ float t[64][65];
    const int n0 = blockIdx.x * 64, c0 = blockIdx.y * 64, b = blockIdx.z;
    const int tid = threadIdx.x;
    const float* xb = x + ((size_t)b * CC + c0) * NN + n0;
    #pragma unroll
    for (int i = tid; i < 1024; i += 256) {
        int r = i >> 4, q = i & 15;
        float4 v = *(const float4*)&xb[(size_t)r * NN + q * 4];
        t[r][q * 4 + 0] = v.x; t[r][q * 4 + 1] = v.y;
        t[r][q * 4 + 2] = v.z; t[r][q * 4 + 3] = v.w;
    }
    __syncthreads();
    #pragma unroll
    for (int i = tid; i < 1024; i += 256) {
        int n = i >> 4, qd = i & 15;
        float v0 = t[qd * 4 + 0][n], v1 = t[qd * 4 + 1][n];
        float v2 = t[qd * 4 + 2][n], v3 = t[qd * 4 + 3][n];
        uint2 uh, ul, uf;
        split2(v0, v1, uh.x, ul.x);
        split2(v2, v3, uh.y, ul.y);
        uf.x = packh2(v0, v1); uf.y = packh2(v2, v3);
        size_t off = ((size_t)b * NN + n0 + n) * CC + c0 + qd * 4;
        *(uint2*)&g_xh[off] = uh;
        *(uint2*)&g_xl[off] = ul;
        *(uint2*)&g_xf[off] = uf;
    }
}

// ---------------------------------------------------------------------------
// Kernel B: weight conversion. [wq;wk] -> split bf16; wv -> fp16.
// ---------------------------------------------------------------------------
__global__ __launch_bounds__(256)
void wconv_kernel(const float* __restrict__ wq, const float* __restrict__ wk,
                  const float* __restrict__ wv) {
    int idx = blockIdx.x * 256 + threadIdx.x;
    if (idx < 128 * 512) {
        int m = idx >> 9, k = idx & 511;
        float v = (m < 64) ? wq[m * 512 + k] : wk[(m - 64) * 512 + k];
        __nv_bfloat16 h = __float2bfloat16_rn(v);
        g_wqkh[idx] = h;
        g_wqkl[idx] = __float2bfloat16_rn(v - __bfloat162float(h));
    } else {
        int j = idx - 65536;
        if (j < 262144) g_wvf[j] = __float2half_rn(wv[j]);
    }
}

// ---------------------------------------------------------------------------
// Kernel C: q/k projection via 3-pass split-bf16 HMMA.
// ---------------------------------------------------------------------------
#define TSTR_H (128 * PSTR)               // 5120 halves per 128x32 stream
#define QK_STG_H (4 * TSTR_H)             // xh | xl | wh | wl
#define QK_SMEM (3 * QK_STG_H * 2)

__global__ __launch_bounds__(256)
void proj_qk_kernel(const float* __restrict__ bq, const float* __restrict__ bk) {
    const int n0 = blockIdx.x * 128, b = blockIdx.z;
    extern __shared__ __align__(16) __nv_bfloat16 qsm[];
    const uint32_t sbase = (uint32_t)__cvta_generic_to_shared(qsm);

    const int tid = threadIdx.x;
    const int wid = tid >> 5, lane = tid & 31;
    const int wm = wid >> 2, wn = wid & 3;
    const int g = lane >> 2, c = lane & 3;

    const __nv_bfloat16* xh = g_xh + ((size_t)b * NN + n0) * CC;
    const __nv_bfloat16* xl = g_xl + ((size_t)b * NN + n0) * CC;

    const int lr = tid >> 1, lc0 = (tid & 1) * 2;

    auto load_tile = [&](int stage, int k0) {
        uint32_t st = sbase + (uint32_t)(stage * QK_STG_H * 2);
        #pragma unroll
        for (int q = 0; q < 2; q++) {
            int c8 = lc0 + q;
            uint32_t so = lr * (PSTR * 2) + c8 * 16;
            cp16(st + so,                 &xh[(size_t)lr * CC + k0 + c8 * 8]);
            cp16(st + TSTR_H * 2 + so,    &xl[(size_t)lr * CC + k0 + c8 * 8]);
            cp16(st + TSTR_H * 4 + so,    &g_wqkh[lr * 512 + k0 + c8 * 8]);
            cp16(st + TSTR_H * 6 + so,    &g_wqkl[lr * 512 + k0 + c8 * 8]);
        }
        CP_COMMIT();
    };

    load_tile(0, 0);
    load_tile(1, 32);

    float acc[4][4][4] = {};
    const int NT = 512 / 32;   // 16

    for (int jt = 0; jt < NT; jt++) {
        if (jt == NT - 1) asm volatile("cp.async.wait_group 0;\n" ::: "memory");
        else              asm volatile("cp.async.wait_group 1;\n" ::: "memory");
        __syncthreads();
        if (jt + 2 < NT) load_tile((jt + 2) % 3, (jt + 2) * 32);

        uint32_t st = sbase + (uint32_t)((jt % 3) * QK_STG_H * 2);
        #pragma unroll
        for (int kc = 0; kc < 2; kc++) {
            uint32_t afh[4][4], afl[4][4], bfh[4][2], bfl[4][2];
            lda4(afh, st,               wm, lane, kc, PSTR);
            lda4(afl, st + TSTR_H * 2,  wm, lane, kc, PSTR);
            ldb4(bfh, st + TSTR_H * 4,  wn, lane, kc, PSTR);
            ldb4(bfl, st + TSTR_H * 6,  wn, lane, kc, PSTR);
            #pragma unroll
            for (int mi = 0; mi < 4; mi++)
                #pragma unroll
                for (int ni = 0; ni < 4; ni++) {
                    MMA_BF16(acc[mi][ni], afh[mi], bfh[ni]);
                    MMA_BF16(acc[mi][ni], afh[mi], bfl[ni]);
                    MMA_BF16(acc[mi][ni], afl[mi], bfh[ni]);
                }
        }
    }

    #pragma unroll
    for (int ni = 0; ni < 4; ni++) {
        int col = wn * 32 + ni * 8 + 2 * c;
        bool isq = (col < 64);
        const float* bb = isq ? bq : bk;
        int cm = col & 63;
        float b0 = bb[cm], b1 = bb[cm + 1];
        __nv_bfloat16* dh = isq ? g_qh : g_kh;
        __nv_bfloat16* dl = isq ? g_ql : g_kl;
        #pragma unroll
        for (int mi = 0; mi < 4; mi++) {
            int r = n0 + wm * 64 + mi * 16 + g;
            uint32_t uh, ul;
            split2(acc[mi][ni][0] + b0, acc[mi][ni][1] + b1, uh, ul);
            size_t o0 = ((size_t)b * NN + r) * MIDD + cm;
            *(uint32_t*)&dh[o0] = uh;
            *(uint32_t*)&dl[o0] = ul;
            split2(acc[mi][ni][2] + b0, acc[mi][ni][3] + b1, uh, ul);
            size_t o1 = ((size_t)b * NN + r + 8) * MIDD + cm;
            *(uint32_t*)&dh[o1] = uh;
            *(uint32_t*)&dl[o1] = ul;
        }
    }
}

// ---------------------------------------------------------------------------
// Kernel D: V projection via single-pass fp16 HMMA.
// ---------------------------------------------------------------------------
#define V_STG_H (2 * TSTR_H)
#define V_SMEM (3 * V_STG_H * 2)

__global__ __launch_bounds__(256)
void proj_v_kernel(const float* __restrict__ bv) {
    const int n0 = blockIdx.x * 128, c0 = blockIdx.y * 128, b = blockIdx.z;
    extern __shared__ __align__(16) __half vsm[];
    const uint32_t sbase = (uint32_t)__cvta_generic_to_shared(vsm);

    const int tid = threadIdx.x;
    const int wid = tid >> 5, lane = tid & 31;
    const int wm = wid >> 2, wn = wid & 3;
    const int g = lane >> 2, c = lane & 3;

    const __half* wv = g_wvf + (size_t)c0 * 512;
    const __half* xf = g_xf + ((size_t)b * NN + n0) * CC;

    const int lr = tid >> 1, lc0 = (tid & 1) * 2;

    auto load_tile = [&](int stage, int k0) {
        uint32_t st = sbase + (uint32_t)(stage * V_STG_H * 2);
        #pragma unroll
        for (int q = 0; q < 2; q++) {
            int c8 = lc0 + q;
            uint32_t so = lr * (PSTR * 2) + c8 * 16;
            cp16(st + so,              &wv[(size_t)lr * 512 + k0 + c8 * 8]);
            cp16(st + TSTR_H * 2 + so, &xf[(size_t)lr * CC + k0 + c8 * 8]);
        }
        CP_COMMIT();
    };

    load_tile(0, 0);
    load_tile(1, 32);

    float acc[4][4][4] = {};
    const int NT = 512 / 32;

    for (int jt = 0; jt < NT; jt++) {
        if (jt == NT - 1) asm volatile("cp.async.wait_group 0;\n" ::: "memory");
        else              asm volatile("cp.async.wait_group 1;\n" ::: "memory");
        __syncthreads();
        if (jt + 2 < NT) load_tile((jt + 2) % 3, (jt + 2) * 32);

        uint32_t st = sbase + (uint32_t)((jt % 3) * V_STG_H * 2);
        #pragma unroll
        for (int kc = 0; kc < 2; kc++) {
            uint32_t af[4][4], bf[4][2];
            lda4(af, st,              wm, lane, kc, PSTR);
            ldb4(bf, st + TSTR_H * 2, wn, lane, kc, PSTR);
            #pragma unroll
            for (int mi = 0; mi < 4; mi++)
                #pragma unroll
                for (int ni = 0; ni < 4; ni++)
                    MMA_F16(acc[mi][ni], af[mi], bf[ni]);
        }
    }

    #pragma unroll
    for (int mi = 0; mi < 4; mi++) {
        int cc = c0 + wm * 64 + mi * 16 + g;
        float b0 = bv[cc], b2 = bv[cc + 8];
        #pragma unroll
        for (int ni = 0; ni < 4; ni++) {
            int nn = n0 + wn * 32 + ni * 8 + 2 * c;
            size_t o0 = ((size_t)b * CC + cc) * NN + nn;
            *(uint32_t*)&g_v[o0] = packh2(acc[mi][ni][0] + b0, acc[mi][ni][1] + b0);
            size_t o1 = o0 + (size_t)8 * NN;
            *(uint32_t*)&g_v[o1] = packh2(acc[mi][ni][2] + b2, acc[mi][ni][3] + b2);
        }
    }
}

// ---------------------------------------------------------------------------
// Kernel 2: logits via split-bf16 HMMA (3 passes), 128x128 CTA tile (R12 shape).
// ---------------------------------------------------------------------------
#define LSTR 72
#define LOGITS_SMEM (4 * 128 * LSTR * 2)

__global__ __launch_bounds__(256)
void logits_kernel() {
    const int j0 = blockIdx.x * 128;
    const int i0 = blockIdx.y * 128;
    const int b  = blockIdx.z;

    extern __shared__ __align__(16) __nv_bfloat16 lsm[];
    __nv_bfloat16* sQh = lsm;
    __nv_bfloat16* sQl = lsm + 128 * LSTR;
    __nv_bfloat16* sKh = lsm + 2 * 128 * LSTR;
    __nv_bfloat16* sKl = lsm + 3 * 128 * LSTR;

    const int tid = threadIdx.x;
    const int wid = tid >> 5, lane = tid & 31;
    const int wm = wid >> 2, wn = wid & 3;
    const int g = lane >> 2, c = lane & 3;

    const size_t qoff = (size_t)b * NN * MIDD;

    #pragma unroll
    for (int i = tid; i < 1024; i += 256) {
        int r = i >> 3, c8 = i & 7;
        size_t go = qoff + (size_t)(i0 + r) * MIDD + c8 * 8;
        size_t ko = qoff + (size_t)(j0 + r) * MIDD + c8 * 8;
        int so = r * LSTR + c8 * 8;
        *(uint4*)&sQh[so] = *(const uint4*)&g_qh[go];
        *(uint4*)&sQl[so] = *(const uint4*)&g_ql[go];
        *(uint4*)&sKh[so] = *(const uint4*)&g_kh[ko];
        *(uint4*)&sKl[so] = *(const uint4*)&g_kl[ko];
    }
    __syncthreads();

    float acc[4][4][4] = {};

    #pragma unroll
    for (int kc = 0; kc < 4; kc++) {
        uint32_t afh[4][4], afl[4][4], bfh[4][2], bfl[4][2];
        #pragma unroll
        for (int mi = 0; mi < 4; mi++) {
            int o = (wm * 64 + mi * 16 + g) * LSTR + kc * 16 + 2 * c;
            afh[mi][0] = *(const uint32_t*)&sQh[o];
            afh[mi][1] = *(const uint32_t*)&sQh[o + 8 * LSTR];
            afh[mi][2] = *(const uint32_t*)&sQh[o + 8];
            afh[mi][3] = *(const uint32_t*)&sQh[o + 8 * LSTR + 8];
            afl[mi][0] = *(const uint32_t*)&sQl[o];
            afl[mi][1] = *(const uint32_t*)&sQl[o + 8 * LSTR];
            afl[mi][2] = *(const uint32_t*)&sQl[o + 8];
            afl[mi][3] = *(const uint32_t*)&sQl[o + 8 * LSTR + 8];
        }
        #pragma unroll
        for (int ni = 0; ni < 4; ni++) {
            int o = (wn * 32 + ni * 8 + g) * LSTR + kc * 16 + 2 * c;
            bfh[ni][0] = *(const uint32_t*)&sKh[o];
            bfh[ni][1] = *(const uint32_t*)&sKh[o + 8];
            bfl[ni][0] = *(const uint32_t*)&sKl[o];
            bfl[ni][1] = *(const uint32_t*)&sKl[o + 8];
        }
        #pragma unroll
        for (int mi = 0; mi < 4; mi++)
            #pragma unroll
            for (int ni = 0; ni < 4; ni++) {
                MMA_BF16(acc[mi][ni], afh[mi], bfh[ni]);
                MMA_BF16(acc[mi][ni], afh[mi], bfl[ni]);
                MMA_BF16(acc[mi][ni], afl[mi], bfh[ni]);
            }
    }

    float* sb = g_s + ((size_t)b * NN + i0) * NN + j0;
    #pragma unroll
    for (int mi = 0; mi < 4; mi++)
        #pragma unroll
        for (int ni = 0; ni < 4; ni++) {
            int r = wm * 64 + mi * 16 + g;
            int cn = wn * 32 + ni * 8 + 2 * c;
            float2 v0 = {acc[mi][ni][0], acc[mi][ni][1]};
            float2 v1 = {acc[mi][ni][2], acc[mi][ni][3]};
            *(float2*)&sb[(size_t)r * NN + cn] = v0;
            *(float2*)&sb[(size_t)(r + 8) * NN + cn] = v1;
        }
}

// ---------------------------------------------------------------------------
// Kernel 3: row softmax, two-phase low-register version (no spills at occ 8).
// Phase A: stream row, keep only running max. Phase B: re-read (L1-hot), exp,
// pack, store immediately. Thread owns 4 contiguous elems x 4 spread groups.
// ---------------------------------------------------------------------------
__global__ __launch_bounds__(256, 8)
void softmax_kernel() {
    const int row = blockIdx.x;
    const int b   = blockIdx.y;
    const float* s = g_s + ((size_t)b * NN + row) * NN;
    __half* p = g_p + ((size_t)b * NN + row) * NN;

    const int tid = threadIdx.x;
    __shared__ float red[8];

    // Phase A: running max only (minimal live registers)
    float m = -3.4e38f;
    #pragma unroll
    for (int gq = 0; gq < 4; gq++) {
        float4 v = *(const float4*)&s[gq * 1024 + tid * 4];
        m = fmaxf(m, fmaxf(fmaxf(v.x, v.y), fmaxf(v.z, v.w)));
    }
    #pragma unroll
    for (int off = 16; off > 0; off >>= 1)
        m = fmaxf(m, __shfl_xor_sync(0xffffffffu, m, off));
    if ((tid & 31) == 0) red[tid >> 5] = m;
    __syncthreads();
    m = red[0];
    #pragma unroll
    for (int w = 1; w < 8; w++) m = fmaxf(m, red[w]);
    __syncthreads();

    // Phase B: re-read (L1 hit), exp, pack, store immediately; accumulate sum
    float sum = 0.f;
    #pragma unroll
    for (int gq = 0; gq < 4; gq++) {
        float4 v = *(const float4*)&s[gq * 1024 + tid * 4];
        v.x = __expf(v.x - m); v.y = __expf(v.y - m);
        v.z = __expf(v.z - m); v.w = __expf(v.w - m);
        sum += (v.x + v.y) + (v.z + v.w);
        uint2 u;
        u.x = packh2(v.x, v.y);
        u.y = packh2(v.z, v.w);
        *(uint2*)&p[gq * 1024 + tid * 4] = u;
    }

    // Row sum -> scale stored probs in a third, register-light pass over g_p
    #pragma unroll
    for (int off = 16; off > 0; off >>= 1)
        sum += __shfl_xor_sync(0xffffffffu, sum, off);
    if ((tid & 31) == 0) red[tid >> 5] = sum;
    __syncthreads();
    sum = 0.f;
    #pragma unroll
    for (int w = 0; w < 8; w++) sum += red[w];
    const float inv = 1.0f / sum;

    #pragma unroll
    for (int gq = 0; gq < 4; gq++) {
        uint2 u = *(const uint2*)&p[gq * 1024 + tid * 4];
        __half2 h0 = *(__half2*)&u.x;
        __half2 h1 = *(__half2*)&u.y;
        float2 f0 = __half22float2(h0);
        float2 f1 = __half22float2(h1);
        u.x = packh2(f0.x * inv, f0.y * inv);
        u.y = packh2(f1.x * inv, f1.y * inv);
        *(uint2*)&p[gq * 1024 + tid * 4] = u;
    }
}

// ---------------------------------------------------------------------------
// Kernel 4: PV via fp16 HMMA, 64x64 warp tiles (CTA 128c x 256n), ldmatrix,
// 3-stage cp.async pipeline.
// Out^T[c][n] = sum_j V[c][j] * P[n][j];  y[b][c][n] = alpha*Out + x.
// ---------------------------------------------------------------------------
#define PV_V_H   (128 * PSTR)
#define PV_P_H   (256 * PSTR)
#define PV_STG_H (PV_V_H + PV_P_H)
#define PV_SMEM  (3 * PV_STG_H * 2)

__global__ __launch_bounds__(256, 1)
void pv_kernel(const float* __restrict__ x,
               const float* __restrict__ alpha,
               float* __restrict__ y) {
    const int n0 = blockIdx.x * 256;
    const int c0 = blockIdx.y * 128;
    const int b  = blockIdx.z;

    extern __shared__ __align__(16) __half psm[];
    const uint32_t sbase = (uint32_t)__cvta_generic_to_shared(psm);

    const int tid = threadIdx.x;
    const int wid = tid >> 5, lane = tid & 31;
    const int wm = wid >> 2, wn = wid & 3;
    const int g = lane >> 2, c = lane & 3;

    const __half* vv = g_v + (size_t)(b * CC + c0) * NN;
    const __half* pp = g_p + ((size_t)b * NN + n0) * NN;

    auto load_tile = [&](int stage, int j0) {
        uint32_t st = sbase + (uint32_t)(stage * PV_STG_H * 2);
        #pragma unroll
        for (int i = tid; i < 512; i += 256) {
            int r = i >> 2, ch = i & 3;
            cp16(st + r * (PSTR * 2) + ch * 16, &vv[(size_t)r * NN + j0 + ch * 8]);
        }
        #pragma unroll
        for (int i = tid; i < 1024; i += 256) {
            int r = i >> 2, ch = i & 3;
            cp16(st + PV_V_H * 2 + r * (PSTR * 2) + ch * 16,
                 &pp[(size_t)r * NN + j0 + ch * 8]);
        }
        CP_COMMIT();
    };

    load_tile(0, 0);
    load_tile(1, 32);

    float acc[4][8][4] = {};
    const int NT = NN / 32;   // 128

    for (int jt = 0; jt < NT; jt++) {
        if (jt == NT - 1) asm volatile("cp.async.wait_group 0;\n" ::: "memory");
        else              asm volatile("cp.async.wait_group 1;\n" ::: "memory");
        __syncthreads();
        if (jt + 2 < NT) load_tile((jt + 2) % 3, (jt + 2) * 32);

        uint32_t st = sbase + (uint32_t)((jt % 3) * PV_STG_H * 2);
        #pragma unroll
        for (int kc = 0; kc < 2; kc++) {
            uint32_t af[4][4], bf[8][2];
            lda4(af, st, wm, lane, kc, PSTR);
            ldb4(bf,     st + PV_V_H * 2, wn * 2,     lane, kc, PSTR);
            ldb4(bf + 4, st + PV_V_H * 2, wn * 2 + 1, lane, kc, PSTR);
            #pragma unroll
            for (int mi = 0; mi < 4; mi++)
                #pragma unroll
                for (int ni = 0; ni < 8; ni++)
                    MMA_F16(acc[mi][ni], af[mi], bf[ni]);
        }
    }

    const float al = __ldg(alpha);
    #pragma unroll
    for (int mi = 0; mi < 4; mi++)
        #pragma unroll
        for (int ni = 0; ni < 8; ni++) {
            int cc = c0 + wm * 64 + mi * 16 + g;
            int nn = n0 + wn * 64 + ni * 8 + 2 * c;
            size_t o0 = ((size_t)b * CC + cc) * NN + nn;
            float2 xv = *(const float2*)&x[o0];
            float2 o;
            o.x = al * acc[mi][ni][0] + xv.x;
            o.y = al * acc[mi][ni][1] + xv.y;
            *(float2*)&y[o0] = o;
            size_t o1 = o0 + (size_t)8 * NN;
            xv = *(const float2*)&x[o1];
            o.x = al * acc[mi][ni][2] + xv.x;
            o.y = al * acc[mi][ni][3] + xv.y;
            *(float2*)&y[o1] = o;
        }
}

// ---------------------------------------------------------------------------
extern "C" void kernel_launch(void* const* d_in, const int* in_sizes, int n_in,
                              void* d_out, int out_size) {
    const float* x     = (const float*)d_in[0];
    const float* wq    = (const float*)d_in[1];
    const float* bq    = (const float*)d_in[2];
    const float* wk    = (const float*)d_in[3];
    const float* bk    = (const float*)d_in[4];
    const float* wv    = (const float*)d_in[5];
    const float* bv    = (const float*)d_in[6];
    const float* alpha = (const float*)d_in[7];
    float* y = (float*)d_out;

    cudaFuncSetAttribute(proj_qk_kernel,
                         cudaFuncAttributeMaxDynamicSharedMemorySize, QK_SMEM);
    cudaFuncSetAttribute(proj_v_kernel,
                         cudaFuncAttributeMaxDynamicSharedMemorySize, V_SMEM);
    cudaFuncSetAttribute(logits_kernel,
                         cudaFuncAttributeMaxDynamicSharedMemorySize, LOGITS_SMEM);
    cudaFuncSetAttribute(pv_kernel,
                         cudaFuncAttributeMaxDynamicSharedMemorySize, PV_SMEM);

    dim3 blk(256);

    xconv_kernel<<<dim3(NN / 64, CC / 64, BB), blk>>>(x);
    wconv_kernel<<<1280, blk>>>(wq, wk, wv);
    proj_qk_kernel<<<dim3(NN / 128, 1, BB), blk, QK_SMEM>>>(bq, bk);
    proj_v_kernel<<<dim3(NN / 128, CC / 128, BB), blk, V_SMEM>>>(bv);
    logits_kernel<<<dim3(NN / 128, NN / 128, BB), blk, LOGITS_SMEM>>>();
    softmax_kernel<<<dim3(NN, BB), blk>>>();
    pv_kernel<<<dim3(NN / 256, CC / 128, BB), blk, PV_SMEM>>>(x, alpha, y);
}